// round 3
// baseline (speedup 1.0000x reference)
#include <cuda_runtime.h>
#include <math.h>

#define B 4096
#define FULL 0xffffffffu
#define NBMAX 4096

// ---------------- scratch (device globals; no allocation allowed) ----------
__device__ float    d_t0[B*14*14*32];   // pooled conv0 output, channel-last
__device__ float    d_p1[B*7*7*32];     // maxpool2(h0) shortcut
__device__ short    d_u1[B*7*7*32];     // pooled binary-conv1 sums (exact ints)
__device__ float    d_p2[B*3*3*32];     // maxpool2(h1)
__device__ short    d_u2[B*3*3*32];     // pooled binary-conv2 sums
__device__ unsigned d_W1b[32*9];
__device__ unsigned d_W2b[32*9];

__device__ float d_psum[NBMAX*32];
__device__ float d_pss [NBMAX*32];
__device__ float d_scale[3*32];
__device__ float d_bias [3*32];

// ---------------- K0: pack binary weights (sign bits) ----------------------
__global__ void packW(const float* __restrict__ w1, const float* __restrict__ w2) {
    int t = threadIdx.x;               // 576 threads
    if (t >= 576) return;
    const float* w = (t < 288) ? w1 : w2;
    unsigned*  dst = (t < 288) ? d_W1b : d_W2b;
    int r = t % 288;
    int o = r / 9, tap = r % 9;
    unsigned word = 0;
#pragma unroll
    for (int c = 0; c < 32; c++)
        word |= (w[o*288 + c*9 + tap] > 0.f ? 1u : 0u) << c;
    dst[o*9 + tap] = word;
}

// ---------------- K1: conv0 (Cin=1, pad=1) + 2x2 maxpool + fused stats -----
// block = one image; 14 warps, warp = pooled row; lane = out channel.
__global__ void __launch_bounds__(448) conv0pool(const float* __restrict__ x,
                                                 const float* __restrict__ w0) {
    __shared__ float xs[30][32];       // zero-padded 28x28 image (+1 border)
    __shared__ float ws[288];
    __shared__ float ss[14][33], sq[14][33];
    int b = blockIdx.x;
    int t = threadIdx.x;

    for (int i = t; i < 960; i += 448) ((float*)xs)[i] = 0.f;
    if (t < 288) ws[t] = w0[t];
    __syncthreads();
    const float* xb = x + b*784;
    for (int i = t; i < 784; i += 448) {
        int r = i / 28;
        xs[r + 1][i - r*28 + 1] = xb[i];
    }
    __syncthreads();

    int lane = t & 31, w = t >> 5;     // w = pooled row py (0..13)
    float wr[9];
#pragma unroll
    for (int k = 0; k < 9; k++) wr[k] = ws[lane*9 + k];

    float s = 0.f, q = 0.f;
    int py = w;
    float* out = d_t0 + (((long)b*14 + py)*14)*32 + lane;
#pragma unroll
    for (int px2 = 0; px2 < 7; px2++) {
        int c0 = 4*px2;
        float xv[4][6];
#pragma unroll
        for (int r = 0; r < 4; r++)
#pragma unroll
            for (int cc = 0; cc < 6; cc++)
                xv[r][cc] = xs[2*py + r][c0 + cc];
#pragma unroll
        for (int tpx = 0; tpx < 2; tpx++) {
            float m = -INFINITY;
#pragma unroll
            for (int dy = 0; dy < 2; dy++)
#pragma unroll
                for (int dx = 0; dx < 2; dx++) {
                    float acc = 0.f;
#pragma unroll
                    for (int ky = 0; ky < 3; ky++)
#pragma unroll
                        for (int kx = 0; kx < 3; kx++)
                            acc = fmaf(wr[ky*3+kx], xv[dy+ky][2*tpx+dx+kx], acc);
                    m = fmaxf(m, acc);
                }
            out[(2*px2 + tpx)*32] = m;
            s += m; q = fmaf(m, m, q);
        }
    }
    ss[w][lane] = s; sq[w][lane] = q;
    __syncthreads();
    if (t < 32) {
        float ts = 0.f, tq = 0.f;
#pragma unroll
        for (int j = 0; j < 14; j++) { ts += ss[j][lane]; tq += sq[j][lane]; }
        d_psum[b*32 + lane] = ts;
        d_pss [b*32 + lane] = tq;
    }
}

// ---------------- K2: finalize BN (parallel) -> per-channel scale/bias -----
__global__ void __launch_bounds__(1024) finalizeBN(int nb, int total,
                           const float* __restrict__ gamma, const float* __restrict__ beta,
                           int stage) {
    __shared__ double sh_s[32][33], sh_q[32][33];
    int c = threadIdx.x & 31, chunk = threadIdx.x >> 5;   // 32 chunks
    double s = 0.0, q = 0.0;
    for (int i = chunk; i < nb; i += 32) {
        s += (double)d_psum[i*32 + c];
        q += (double)d_pss [i*32 + c];
    }
    sh_s[chunk][c] = s; sh_q[chunk][c] = q;
    __syncthreads();
    if (threadIdx.x < 32) {
        double ts = 0.0, tq = 0.0;
#pragma unroll
        for (int j = 0; j < 32; j++) { ts += sh_s[j][c]; tq += sh_q[j][c]; }
        double n    = (double)total / 32.0;
        double mean = ts / n;
        double var  = tq / n - mean * mean;
        double sc   = (double)gamma[c] / sqrt(var + 1e-5);
        d_scale[stage*32 + c] = (float)sc;
        d_bias [stage*32 + c] = (float)((double)beta[c] - mean * sc);
    }
}

// ---------------- K3: bn(t0)->X1(smem), p1, binary conv1 + pool + stats ----
// block = one image, 256 threads (8 warps), lane = channel.
__global__ void __launch_bounds__(256) kB() {
    __shared__ float    hs[196][32];    // h0 = bn(t0), 25KB
    __shared__ unsigned X1p[16][16];    // zero-padded sign bitmap
    __shared__ float    ss[8][33], sq[8][33];
    int b = blockIdx.x;
    int t = threadIdx.x;
    int lane = t & 31, w = t >> 5;

    ((unsigned*)X1p)[t] = 0u;           // 256 entries exactly
    __syncthreads();

    float sc = d_scale[lane], bs = d_bias[lane];
    const float* t0b = d_t0 + (long)b * 196 * 32;
    for (int pix = w; pix < 196; pix += 8) {
        float h = fmaf(sc, t0b[pix*32 + lane], bs);
        hs[pix][lane] = h;
        unsigned bal = __ballot_sync(FULL, h > 0.f);
        if (lane == 0) X1p[pix/14 + 1][pix%14 + 1] = bal;
    }
    __syncthreads();

    // p1 = maxpool2(h0)
    float* p1b = d_p1 + b * 49 * 32;
    for (int j = w; j < 49; j += 8) {
        int py = j / 7, px = j % 7;
        int i0 = (2*py)*14 + 2*px;
        float m = fmaxf(fmaxf(hs[i0][lane],     hs[i0+1][lane]),
                        fmaxf(hs[i0+14][lane],  hs[i0+15][lane]));
        p1b[j*32 + lane] = m;
    }

    // binary conv1 (xor+popc) + pool, from smem bitmap
    unsigned wb[9];
    int Kc[9];
#pragma unroll
    for (int k = 0; k < 9; k++) { wb[k] = d_W1b[lane*9 + k]; Kc[k] = 32 - 2*__popc(wb[k]); }
    int Kt = Kc[0]+Kc[1]+Kc[2], Kb = Kc[6]+Kc[7]+Kc[8];
    int Kl = Kc[0]+Kc[3]+Kc[6], Kr = Kc[2]+Kc[5]+Kc[8];

    float s = 0.f, q = 0.f;
    short* u1b = d_u1 + b * 49 * 32;
    for (int j = w; j < 49; j += 8) {
        int py = j / 7, px = j % 7;
        unsigned xw[4][4];
#pragma unroll
        for (int r = 0; r < 4; r++)
#pragma unroll
            for (int c = 0; c < 4; c++)
                xw[r][c] = X1p[2*py + r][2*px + c];
        int m = -100000;
#pragma unroll
        for (int dy = 0; dy < 2; dy++)
#pragma unroll
            for (int dx = 0; dx < 2; dx++) {
                int sump = 0;
#pragma unroll
                for (int ky = 0; ky < 3; ky++)
#pragma unroll
                    for (int kx = 0; kx < 3; kx++)
                        sump += __popc(xw[dy+ky][dx+kx] ^ wb[ky*3+kx]);
                int v = 288 - 2*sump;
                bool top = (py == 0) && (dy == 0);
                bool bot = (py == 6) && (dy == 1);
                bool lef = (px == 0) && (dx == 0);
                bool rig = (px == 6) && (dx == 1);
                int corr = 0;
                if (top) corr += Kt;
                if (bot) corr += Kb;
                if (lef) corr += Kl;
                if (rig) corr += Kr;
                if (top && lef) corr -= Kc[0];
                if (top && rig) corr -= Kc[2];
                if (bot && lef) corr -= Kc[6];
                if (bot && rig) corr -= Kc[8];
                m = max(m, v - corr);
            }
        u1b[j*32 + lane] = (short)m;
        float fm = (float)m;
        s += fm; q = fmaf(fm, fm, q);
    }
    ss[w][lane] = s; sq[w][lane] = q;
    __syncthreads();
    if (t < 32) {
        float ts = 0.f, tq = 0.f;
#pragma unroll
        for (int j = 0; j < 8; j++) { ts += ss[j][lane]; tq += sq[j][lane]; }
        d_psum[b*32 + lane] = ts;
        d_pss [b*32 + lane] = tq;
    }
}

// ---------------- K4: h1=bn(u1)+p1 -> X2(smem), p2, binary conv2 + stats ---
// block = one image, 256 threads (8 warps), lane = channel.
__global__ void __launch_bounds__(256) kC() {
    __shared__ float    h1s[49][32];
    __shared__ unsigned X2p[9][9];
    __shared__ float    ss[8][33], sq[8][33];
    int b = blockIdx.x;
    int t = threadIdx.x;
    int lane = t & 31, w = t >> 5;

    if (t < 81) ((unsigned*)X2p)[t] = 0u;
    __syncthreads();

    float sc = d_scale[32 + lane], bs = d_bias[32 + lane];
    const short* u1b = d_u1 + b * 49 * 32;
    const float* p1b = d_p1 + b * 49 * 32;
    for (int j = w; j < 49; j += 8) {
        float h = fmaf(sc, (float)u1b[j*32 + lane], bs) + p1b[j*32 + lane];
        h1s[j][lane] = h;
        unsigned bal = __ballot_sync(FULL, h > 0.f);
        if (lane == 0) X2p[j/7 + 1][j%7 + 1] = bal;
    }
    __syncthreads();

    // p2 = maxpool2(h1) (7->3 floor)
    float* p2b = d_p2 + b * 9 * 32;
    for (int j = w; j < 9; j += 8) {
        int py = j / 3, px = j % 3;
        int i0 = (2*py)*7 + 2*px;
        float m = fmaxf(fmaxf(h1s[i0][lane],    h1s[i0+1][lane]),
                        fmaxf(h1s[i0+7][lane],  h1s[i0+8][lane]));
        p2b[j*32 + lane] = m;
    }

    // binary conv2 + pool. cy,cx <= 5 so only top/left borders can occur.
    unsigned wb[9];
    int Kc0, Kc1, Kc2, Kc3, Kc6, Kt, Kl;
#pragma unroll
    for (int k = 0; k < 9; k++) wb[k] = d_W2b[lane*9 + k];
    Kc0 = 32 - 2*__popc(wb[0]);
    Kc1 = 32 - 2*__popc(wb[1]);
    Kc2 = 32 - 2*__popc(wb[2]);
    Kc3 = 32 - 2*__popc(wb[3]);
    Kc6 = 32 - 2*__popc(wb[6]);
    Kt = Kc0 + Kc1 + Kc2;
    Kl = Kc0 + Kc3 + Kc6;

    float s = 0.f, q = 0.f;
    short* u2b = d_u2 + b * 9 * 32;
    for (int j = w; j < 9; j += 8) {
        int py = j / 3, px = j % 3;
        unsigned xw[4][4];
#pragma unroll
        for (int r = 0; r < 4; r++)
#pragma unroll
            for (int c = 0; c < 4; c++)
                xw[r][c] = X2p[2*py + r][2*px + c];
        int m = -100000;
#pragma unroll
        for (int dy = 0; dy < 2; dy++)
#pragma unroll
            for (int dx = 0; dx < 2; dx++) {
                int sump = 0;
#pragma unroll
                for (int ky = 0; ky < 3; ky++)
#pragma unroll
                    for (int kx = 0; kx < 3; kx++)
                        sump += __popc(xw[dy+ky][dx+kx] ^ wb[ky*3+kx]);
                int v = 288 - 2*sump;
                bool top = (py == 0) && (dy == 0);
                bool lef = (px == 0) && (dx == 0);
                int corr = 0;
                if (top) corr += Kt;
                if (lef) corr += Kl;
                if (top && lef) corr -= Kc0;
                m = max(m, v - corr);
            }
        u2b[j*32 + lane] = (short)m;
        float fm = (float)m;
        s += fm; q = fmaf(fm, fm, q);
    }
    ss[w][lane] = s; sq[w][lane] = q;
    __syncthreads();
    if (t < 32) {
        float ts = 0.f, tq = 0.f;
#pragma unroll
        for (int j = 0; j < 8; j++) { ts += ss[j][lane]; tq += sq[j][lane]; }
        d_psum[b*32 + lane] = ts;
        d_pss [b*32 + lane] = tq;
    }
}

// ---------------- K5: fused h2 = bn(u2)+p2, flatten, FC --------------------
__global__ void fc_kernel(const float* __restrict__ fw, const float* __restrict__ fb,
                          float* __restrict__ out) {
    int wid = (blockIdx.x * blockDim.x + threadIdx.x) >> 5;   // = b
    int c   = threadIdx.x & 31;
    float sc = d_scale[64 + c], bs = d_bias[64 + c];
    float acc[10];
#pragma unroll
    for (int k = 0; k < 10; k++) acc[k] = 0.f;
#pragma unroll
    for (int ij = 0; ij < 9; ij++) {
        int i = (wid*9 + ij)*32 + c;
        float h = fmaf(sc, (float)d_u2[i], bs) + d_p2[i];
#pragma unroll
        for (int k = 0; k < 10; k++)
            acc[k] = fmaf(h, fw[k*288 + c*9 + ij], acc[k]);
    }
#pragma unroll
    for (int k = 0; k < 10; k++) {
#pragma unroll
        for (int off = 16; off; off >>= 1)
            acc[k] += __shfl_xor_sync(FULL, acc[k], off);
        if (c == k) out[wid*10 + k] = acc[k] + fb[k];
    }
}

// ---------------- launch ----------------------------------------------------
extern "C" void kernel_launch(void* const* d_in, const int* in_sizes, int n_in,
                              void* d_out, int out_size) {
    const float* x  = (const float*)d_in[0];
    const float* w0 = (const float*)d_in[1];
    const float* g0 = (const float*)d_in[2];
    const float* b0 = (const float*)d_in[3];
    const float* w1 = (const float*)d_in[4];
    const float* g1 = (const float*)d_in[5];
    const float* b1 = (const float*)d_in[6];
    const float* w2 = (const float*)d_in[7];
    const float* g2 = (const float*)d_in[8];
    const float* b2 = (const float*)d_in[9];
    const float* fw = (const float*)d_in[10];
    const float* fb = (const float*)d_in[11];
    float* out = (float*)d_out;

    const int T0 = B*14*14*32;   // 25,690,112
    const int T1 = B*7*7*32;     //  6,422,528
    const int T2 = B*3*3*32;     //  1,179,648

    packW<<<1, 576>>>(w1, w2);

    conv0pool<<<B, 448>>>(x, w0);
    finalizeBN<<<1, 1024>>>(B, T0, g0, b0, 0);

    kB<<<B, 256>>>();
    finalizeBN<<<1, 1024>>>(B, T1, g1, b1, 1);

    kC<<<B, 256>>>();
    finalizeBN<<<1, 1024>>>(B, T2, g2, b2, 2);

    fc_kernel<<<(B*32)/256, 256>>>(fw, fb, out);
}

// round 4
// speedup vs baseline: 1.3507x; 1.3507x over previous
#include <cuda_runtime.h>
#include <math.h>

#define B 4096
#define FULL 0xffffffffu
#define NBMAX 4096

// ---------------- scratch (device globals; no allocation allowed) ----------
__device__ float    d_t0[B*14*14*32];   // pooled conv0 output, channel-last
__device__ unsigned d_X1[B*16*16];      // packed sign(h0) bits, zero-padded 16x16
__device__ float    d_p1[B*7*7*32];     // maxpool2(h0) shortcut
__device__ short    d_u1[B*7*7*32];     // pooled binary-conv1 sums (exact ints)
__device__ unsigned d_X2[B*9*9];        // packed sign(h1) bits, zero-padded 9x9
__device__ float    d_p2[B*3*3*32];     // maxpool2(h1)
__device__ short    d_u2[B*3*3*32];     // pooled binary-conv2 sums
__device__ unsigned d_W1b[32*9];
__device__ unsigned d_W2b[32*9];

__device__ float d_psum[32*NBMAX];      // transposed: [channel][block]
__device__ float d_pss [32*NBMAX];
__device__ float d_scale[3*32];
__device__ float d_bias [3*32];

// ---------------- f32x2 packed-math helpers --------------------------------
__device__ __forceinline__ unsigned long long pk2(float lo, float hi) {
    unsigned long long r;
    asm("mov.b64 %0, {%1, %2};" : "=l"(r) : "f"(lo), "f"(hi));
    return r;
}
__device__ __forceinline__ unsigned long long fma2(unsigned long long a,
                                                   unsigned long long b,
                                                   unsigned long long c) {
    unsigned long long d;
    asm("fma.rn.f32x2 %0, %1, %2, %3;" : "=l"(d) : "l"(a), "l"(b), "l"(c));
    return d;
}
__device__ __forceinline__ void upk2(unsigned long long v, float& lo, float& hi) {
    asm("mov.b64 {%0, %1}, %2;" : "=f"(lo), "=f"(hi) : "l"(v));
}

// ---------------- K1: conv0 (Cin=1, pad=1) + 2x2 maxpool + stats + packW ---
// block = one image; 14 warps, warp = pooled row; lane = out channel.
// Inner conv uses fma.rn.f32x2 on adjacent full-res output-column pairs.
__global__ void __launch_bounds__(448) conv0pool(const float* __restrict__ x,
                                                 const float* __restrict__ w0,
                                                 const float* __restrict__ w1,
                                                 const float* __restrict__ w2) {
    __shared__ float xs[30][32];       // zero-padded 28x28 image (+1 border)
    __shared__ float ws[288];
    __shared__ float ss[14][33], sq[14][33];
    int b = blockIdx.x;
    int t = threadIdx.x;

    for (int i = t; i < 960; i += 448) ((float*)xs)[i] = 0.f;
    if (t < 288) ws[t] = w0[t];
    __syncthreads();
    const float* xb = x + b*784;
    for (int i = t; i < 784; i += 448) {
        int r = i / 28;
        xs[r + 1][i - r*28 + 1] = xb[i];
    }
    __syncthreads();

    int lane = t & 31, py = t >> 5;    // py = pooled row (0..13)
    unsigned long long wp[9];
#pragma unroll
    for (int k = 0; k < 9; k++) { float wv = ws[lane*9 + k]; wp[k] = pk2(wv, wv); }

    float s = 0.f, q = 0.f;
    float* out = d_t0 + (((long)b*14 + py)*14)*32 + lane;
#pragma unroll
    for (int j2 = 0; j2 < 7; j2++) {   // strip = 2 pooled pixels
        unsigned long long a00 = 0ull, a01 = 0ull, a10 = 0ull, a11 = 0ull;
#pragma unroll
        for (int r = 0; r < 4; r++) {
            float e0 = xs[2*py + r][4*j2 + 0];
            float e1 = xs[2*py + r][4*j2 + 1];
            float e2 = xs[2*py + r][4*j2 + 2];
            float e3 = xs[2*py + r][4*j2 + 3];
            float e4 = xs[2*py + r][4*j2 + 4];
            float e5 = xs[2*py + r][4*j2 + 5];
            unsigned long long Q0 = pk2(e0, e1), Q1 = pk2(e1, e2), Q2 = pk2(e2, e3),
                               Q3 = pk2(e3, e4), Q4 = pk2(e4, e5);
            if (r < 3) {               // dy=0 row, ky=r
                a00 = fma2(wp[r*3+0], Q0, a00);
                a00 = fma2(wp[r*3+1], Q1, a00);
                a00 = fma2(wp[r*3+2], Q2, a00);
                a01 = fma2(wp[r*3+0], Q2, a01);
                a01 = fma2(wp[r*3+1], Q3, a01);
                a01 = fma2(wp[r*3+2], Q4, a01);
            }
            if (r >= 1) {              // dy=1 row, ky=r-1
                int k = (r-1)*3;
                a10 = fma2(wp[k+0], Q0, a10);
                a10 = fma2(wp[k+1], Q1, a10);
                a10 = fma2(wp[k+2], Q2, a10);
                a11 = fma2(wp[k+0], Q2, a11);
                a11 = fma2(wp[k+1], Q3, a11);
                a11 = fma2(wp[k+2], Q4, a11);
            }
        }
        float l0, h0, l1, h1;
        upk2(a00, l0, h0); upk2(a10, l1, h1);
        float m0 = fmaxf(fmaxf(l0, h0), fmaxf(l1, h1));
        upk2(a01, l0, h0); upk2(a11, l1, h1);
        float m1 = fmaxf(fmaxf(l0, h0), fmaxf(l1, h1));
        out[(2*j2 + 0)*32] = m0;
        out[(2*j2 + 1)*32] = m1;
        s += m0 + m1;
        q = fmaf(m0, m0, q); q = fmaf(m1, m1, q);
    }
    ss[py][lane] = s; sq[py][lane] = q;

    // fused weight packing (block 0 only, independent of conv work)
    if (b == 0) {
        for (int i = t; i < 576; i += 448) {
            const float* w = (i < 288) ? w1 : w2;
            unsigned*  dst = (i < 288) ? d_W1b : d_W2b;
            int rr = i % 288;
            int o = rr / 9, tap = rr % 9;
            unsigned word = 0;
#pragma unroll
            for (int c = 0; c < 32; c++)
                word |= (w[o*288 + c*9 + tap] > 0.f ? 1u : 0u) << c;
            dst[o*9 + tap] = word;
        }
    }
    __syncthreads();
    if (t < 32) {
        float ts = 0.f, tq = 0.f;
#pragma unroll
        for (int j = 0; j < 14; j++) { ts += ss[j][t]; tq += sq[j][t]; }
        d_psum[t*NBMAX + b] = ts;
        d_pss [t*NBMAX + b] = tq;
    }
}

// ---------------- K2: finalize BN (coalesced, MLP-unrolled) ----------------
__global__ void __launch_bounds__(1024) finalizeBN(int nb, int total,
                           const float* __restrict__ gamma, const float* __restrict__ beta,
                           int stage) {
    int c  = threadIdx.x >> 5;         // channel (warp per channel)
    int i0 = threadIdx.x & 31;
    const float* ps = d_psum + c*NBMAX;
    const float* pq = d_pss  + c*NBMAX;
    double s0 = 0, s1 = 0, s2 = 0, s3 = 0, q0 = 0, q1 = 0, q2 = 0, q3 = 0;
    for (int base = i0; base < nb; base += 128) {
        s0 += (double)ps[base];      q0 += (double)pq[base];
        if (base + 32 < nb) { s1 += (double)ps[base+32]; q1 += (double)pq[base+32]; }
        if (base + 64 < nb) { s2 += (double)ps[base+64]; q2 += (double)pq[base+64]; }
        if (base + 96 < nb) { s3 += (double)ps[base+96]; q3 += (double)pq[base+96]; }
    }
    double s = (s0 + s1) + (s2 + s3);
    double q = (q0 + q1) + (q2 + q3);
#pragma unroll
    for (int off = 16; off; off >>= 1) {
        s += __shfl_xor_sync(FULL, s, off);
        q += __shfl_xor_sync(FULL, q, off);
    }
    if (i0 == 0) {
        double n    = (double)total / 32.0;
        double mean = s / n;
        double var  = q / n - mean * mean;
        double sc   = (double)gamma[c] / sqrt(var + 1e-5);
        d_scale[stage*32 + c] = (float)sc;
        d_bias [stage*32 + c] = (float)((double)beta[c] - mean * sc);
    }
}

// border map for 16x16 padded bitmap (60 border words)
__device__ __forceinline__ void bmap16(int i, int& row, int& col) {
    if (i < 16)      { row = 0;      col = i;      }
    else if (i < 32) { row = 15;     col = i - 16; }
    else if (i < 46) { row = i - 31; col = 0;      }
    else             { row = i - 45; col = 15;     }
}

// ---------------- K3: bn(t0) -> sign-pack X1(padded) + shortcut pool p1 ----
__global__ void pack1() {
    int wid  = (blockIdx.x * blockDim.x + threadIdx.x) >> 5;   // B*49 exact
    int lane = threadIdx.x & 31;
    int b  = wid / 49;
    int r  = wid % 49;
    int py = r / 7, px = r % 7;
    float sc = d_scale[lane], bs = d_bias[lane];
    float hmax = -INFINITY;
    unsigned myw = 0;
#pragma unroll
    for (int d = 0; d < 4; d++) {
        int y = 2*py + (d >> 1), x = 2*px + (d & 1);
        float v = d_t0[(((long)b*14 + y)*14 + x)*32 + lane];
        float h = fmaf(sc, v, bs);
        unsigned bal = __ballot_sync(FULL, h > 0.f);
        if (lane == d) myw = bal;
        hmax = fmaxf(hmax, h);
    }
    if (lane < 4) {
        int y = 2*py + (lane >> 1) + 1, x = 2*px + (lane & 1) + 1;
        d_X1[b*256 + y*16 + x] = myw;
    }
    d_p1[((b*7 + py)*7 + px)*32 + lane] = hmax;
    if (r == 0) {                      // one warp per image zeroes 60 border words
        int row, col;
        bmap16(lane, row, col);
        d_X1[b*256 + row*16 + col] = 0u;
        if (lane + 32 < 60) {
            bmap16(lane + 32, row, col);
            d_X1[b*256 + row*16 + col] = 0u;
        }
    }
}

// ---------------- K4: binary conv1 (14x14 padded) + pool + stats -----------
__global__ void __launch_bounds__(256) bconv14() {
    int lane = threadIdx.x & 31;       // == out channel o
    unsigned wb[9]; int Kc[9];
#pragma unroll
    for (int k = 0; k < 9; k++) { wb[k] = d_W1b[lane*9 + k]; Kc[k] = 32 - 2*__popc(wb[k]); }
    int Kt = Kc[0]+Kc[1]+Kc[2], Kb = Kc[6]+Kc[7]+Kc[8];
    int Kl = Kc[0]+Kc[3]+Kc[6], Kr = Kc[2]+Kc[5]+Kc[8];

    float s = 0.f, q = 0.f;
    int stride = blockDim.x * gridDim.x;
    const int total = B*49*32;
    for (int gid = blockIdx.x * blockDim.x + threadIdx.x; gid < total; gid += stride) {
        int wid = gid >> 5;
        int b  = wid / 49;
        int r  = wid % 49;
        int py = r / 7, px = r % 7;
        const unsigned* Xb = d_X1 + b * 256;
        unsigned xw[4][4];
#pragma unroll
        for (int r4 = 0; r4 < 4; r4++)
#pragma unroll
            for (int c4 = 0; c4 < 4; c4++)
                xw[r4][c4] = Xb[(2*py + r4)*16 + 2*px + c4];
        int vv[4];
#pragma unroll
        for (int dy = 0; dy < 2; dy++)
#pragma unroll
            for (int dx = 0; dx < 2; dx++) {
                int sump = 0;
#pragma unroll
                for (int ky = 0; ky < 3; ky++)
#pragma unroll
                    for (int kx = 0; kx < 3; kx++)
                        sump += __popc(xw[dy+ky][dx+kx] ^ wb[ky*3+kx]);
                vv[dy*2+dx] = 288 - 2*sump;
            }
        if (py == 0 || py == 6 || px == 0 || px == 6) {   // warp-uniform branch
#pragma unroll
            for (int dy = 0; dy < 2; dy++)
#pragma unroll
                for (int dx = 0; dx < 2; dx++) {
                    bool top = (py == 0) && (dy == 0);
                    bool bot = (py == 6) && (dy == 1);
                    bool lef = (px == 0) && (dx == 0);
                    bool rig = (px == 6) && (dx == 1);
                    int corr = 0;
                    if (top) corr += Kt;
                    if (bot) corr += Kb;
                    if (lef) corr += Kl;
                    if (rig) corr += Kr;
                    if (top && lef) corr -= Kc[0];
                    if (top && rig) corr -= Kc[2];
                    if (bot && lef) corr -= Kc[6];
                    if (bot && rig) corr -= Kc[8];
                    vv[dy*2+dx] -= corr;
                }
        }
        int m = max(max(vv[0], vv[1]), max(vv[2], vv[3]));
        d_u1[gid] = (short)m;
        float fm = (float)m;
        s += fm; q = fmaf(fm, fm, q);
    }
    __shared__ float ss[8][33], sq[8][33];
    int w = threadIdx.x >> 5;
    ss[w][lane] = s; sq[w][lane] = q;
    __syncthreads();
    if (threadIdx.x < 32) {
        float ts = 0.f, tq = 0.f;
#pragma unroll
        for (int j = 0; j < 8; j++) { ts += ss[j][threadIdx.x]; tq += sq[j][threadIdx.x]; }
        d_psum[threadIdx.x*NBMAX + blockIdx.x] = ts;
        d_pss [threadIdx.x*NBMAX + blockIdx.x] = tq;
    }
}

// border map for 9x9 padded bitmap (32 border words)
__device__ __forceinline__ void bmap9(int i, int& row, int& col) {
    if (i < 9)       { row = 0;      col = i;     }
    else if (i < 18) { row = 8;      col = i - 9; }
    else if (i < 25) { row = i - 17; col = 0;     }
    else             { row = i - 24; col = 8;     }
}

// ---------------- K5: h1 = bn(u1)+p1 -> X2(padded) pack + p2 pool ----------
// 16 warps per image: warps 0..8 = 3x3 pooling windows, 9..15 = 13 rest pixels.
__global__ void h1_fuse() {
    int gw   = (blockIdx.x * blockDim.x + threadIdx.x) >> 5;   // B*16 exact
    int lane = threadIdx.x & 31;
    int b = gw >> 4;
    int j = gw & 15;
    float sc = d_scale[32 + lane], bs = d_bias[32 + lane];
    if (j < 9) {
        int py = j / 3, px = j % 3;
        float hmax = -INFINITY;
        unsigned myw = 0;
#pragma unroll
        for (int d = 0; d < 4; d++) {
            int y = 2*py + (d >> 1), x = 2*px + (d & 1);
            int i = ((b*7 + y)*7 + x)*32 + lane;
            float h = fmaf(sc, (float)d_u1[i], bs) + d_p1[i];
            unsigned bal = __ballot_sync(FULL, h > 0.f);
            if (lane == d) myw = bal;
            hmax = fmaxf(hmax, h);
        }
        if (lane < 4) {
            int y = 2*py + (lane >> 1) + 1, x = 2*px + (lane & 1) + 1;
            d_X2[b*81 + y*9 + x] = myw;
        }
        d_p2[((b*3 + py)*3 + px)*32 + lane] = hmax;
    } else {
        int k = j - 9;
#pragma unroll
        for (int e = 0; e < 2; e++) {
            int pi = 2*k + e;
            if (pi < 13) {                       // warp-uniform branch
                int y = (pi < 6) ? pi : 6;
                int x = (pi < 6) ? 6  : (pi - 6);
                int i = ((b*7 + y)*7 + x)*32 + lane;
                float h = fmaf(sc, (float)d_u1[i], bs) + d_p1[i];
                unsigned bal = __ballot_sync(FULL, h > 0.f);
                if (lane == 0) d_X2[b*81 + (y+1)*9 + (x+1)] = bal;
            }
        }
        if (j == 15) {                 // zero the 32 border words
            int row, col;
            bmap9(lane, row, col);
            d_X2[b*81 + row*9 + col] = 0u;
        }
    }
}

// ---------------- K6: binary conv2 (7x7 padded) + pool + stats -------------
__global__ void __launch_bounds__(256) bconv7() {
    int lane = threadIdx.x & 31;
    unsigned wb[9];
#pragma unroll
    for (int k = 0; k < 9; k++) wb[k] = d_W2b[lane*9 + k];
    int Kc0 = 32 - 2*__popc(wb[0]);
    int Kc1 = 32 - 2*__popc(wb[1]);
    int Kc2 = 32 - 2*__popc(wb[2]);
    int Kc3 = 32 - 2*__popc(wb[3]);
    int Kc6 = 32 - 2*__popc(wb[6]);
    int Kt = Kc0 + Kc1 + Kc2;
    int Kl = Kc0 + Kc3 + Kc6;

    float s = 0.f, q = 0.f;
    int stride = blockDim.x * gridDim.x;
    const int total = B*9*32;
    for (int gid = blockIdx.x * blockDim.x + threadIdx.x; gid < total; gid += stride) {
        int wid = gid >> 5;
        int b  = wid / 9;
        int r  = wid % 9;
        int py = r / 3, px = r % 3;
        const unsigned* Xb = d_X2 + b * 81;
        unsigned xw[4][4];
#pragma unroll
        for (int r4 = 0; r4 < 4; r4++)
#pragma unroll
            for (int c4 = 0; c4 < 4; c4++)
                xw[r4][c4] = Xb[(2*py + r4)*9 + 2*px + c4];
        int m = -100000;
#pragma unroll
        for (int dy = 0; dy < 2; dy++)
#pragma unroll
            for (int dx = 0; dx < 2; dx++) {
                int sump = 0;
#pragma unroll
                for (int ky = 0; ky < 3; ky++)
#pragma unroll
                    for (int kx = 0; kx < 3; kx++)
                        sump += __popc(xw[dy+ky][dx+kx] ^ wb[ky*3+kx]);
                int v = 288 - 2*sump;
                bool top = (py == 0) && (dy == 0);
                bool lef = (px == 0) && (dx == 0);
                int corr = 0;
                if (top) corr += Kt;
                if (lef) corr += Kl;
                if (top && lef) corr -= Kc0;
                m = max(m, v - corr);
            }
        d_u2[gid] = (short)m;
        float fm = (float)m;
        s += fm; q = fmaf(fm, fm, q);
    }
    __shared__ float ss[8][33], sq[8][33];
    int w = threadIdx.x >> 5;
    ss[w][lane] = s; sq[w][lane] = q;
    __syncthreads();
    if (threadIdx.x < 32) {
        float ts = 0.f, tq = 0.f;
#pragma unroll
        for (int j = 0; j < 8; j++) { ts += ss[j][threadIdx.x]; tq += sq[j][threadIdx.x]; }
        d_psum[threadIdx.x*NBMAX + blockIdx.x] = ts;
        d_pss [threadIdx.x*NBMAX + blockIdx.x] = tq;
    }
}

// ---------------- K7: fused h2 = bn(u2)+p2, flatten, FC --------------------
__global__ void fc_kernel(const float* __restrict__ fw, const float* __restrict__ fb,
                          float* __restrict__ out) {
    int wid = (blockIdx.x * blockDim.x + threadIdx.x) >> 5;   // = b
    int c   = threadIdx.x & 31;
    float sc = d_scale[64 + c], bs = d_bias[64 + c];
    float acc[10];
#pragma unroll
    for (int k = 0; k < 10; k++) acc[k] = 0.f;
#pragma unroll
    for (int ij = 0; ij < 9; ij++) {
        int i = (wid*9 + ij)*32 + c;
        float h = fmaf(sc, (float)d_u2[i], bs) + d_p2[i];
#pragma unroll
        for (int k = 0; k < 10; k++)
            acc[k] = fmaf(h, fw[k*288 + c*9 + ij], acc[k]);
    }
#pragma unroll
    for (int k = 0; k < 10; k++) {
#pragma unroll
        for (int off = 16; off; off >>= 1)
            acc[k] += __shfl_xor_sync(FULL, acc[k], off);
        if (c == k) out[wid*10 + k] = acc[k] + fb[k];
    }
}

// ---------------- launch ----------------------------------------------------
extern "C" void kernel_launch(void* const* d_in, const int* in_sizes, int n_in,
                              void* d_out, int out_size) {
    const float* x  = (const float*)d_in[0];
    const float* w0 = (const float*)d_in[1];
    const float* g0 = (const float*)d_in[2];
    const float* b0 = (const float*)d_in[3];
    const float* w1 = (const float*)d_in[4];
    const float* g1 = (const float*)d_in[5];
    const float* b1 = (const float*)d_in[6];
    const float* w2 = (const float*)d_in[7];
    const float* g2 = (const float*)d_in[8];
    const float* b2 = (const float*)d_in[9];
    const float* fw = (const float*)d_in[10];
    const float* fb = (const float*)d_in[11];
    float* out = (float*)d_out;

    const int T0 = B*14*14*32;   // 25,690,112
    const int T1 = B*7*7*32;     //  6,422,528
    const int T2 = B*3*3*32;     //  1,179,648
    const int NB = 1184;

    conv0pool<<<B, 448>>>(x, w0, w1, w2);
    finalizeBN<<<1, 1024>>>(B, T0, g0, b0, 0);

    pack1<<<(B*49*32)/256, 256>>>();
    bconv14<<<NB, 256>>>();
    finalizeBN<<<1, 1024>>>(NB, T1, g1, b1, 1);

    h1_fuse<<<(B*16*32)/256, 256>>>();
    bconv7<<<NB, 256>>>();
    finalizeBN<<<1, 1024>>>(NB, T2, g2, b2, 2);

    fc_kernel<<<(B*32)/256, 256>>>(fw, fb, out);
}

// round 5
// speedup vs baseline: 1.3925x; 1.0310x over previous
#include <cuda_runtime.h>
#include <math.h>

#define B 4096
#define GRID 148
#define NT 448                 // 14 warps
#define FULL 0xffffffffu

// ---------------- device scratch (no allocation allowed) -------------------
__device__ float d_t0[B*14*14*32];     // pooled conv0 output, channel-last
__device__ float d_p1[B*7*7*32];       // maxpool2(h0) shortcut
__device__ float d_u1[B*7*7*32];       // binary-conv1 pooled sums (exact ints)
__device__ float d_p2[B*3*3*32];       // maxpool2(h1)
__device__ float d_u2[B*3*3*32];       // binary-conv2 pooled sums
__device__ float d_psA[3][32*GRID];    // per-stage per-block stats partials
__device__ float d_pqA[3][32*GRID];
__device__ int   d_bar[4];             // monotonic barrier counters (zero-init)

// ---------------- helpers ---------------------------------------------------
__device__ __forceinline__ unsigned long long pk2(float lo, float hi) {
    unsigned long long r;
    asm("mov.b64 %0, {%1, %2};" : "=l"(r) : "f"(lo), "f"(hi));
    return r;
}
__device__ __forceinline__ unsigned long long fma2(unsigned long long a,
                                                   unsigned long long b,
                                                   unsigned long long c) {
    unsigned long long d;
    asm("fma.rn.f32x2 %0, %1, %2, %3;" : "=l"(d) : "l"(a), "l"(b), "l"(c));
    return d;
}
__device__ __forceinline__ void upk2(unsigned long long v, float& lo, float& hi) {
    asm("mov.b64 {%0, %1}, %2;" : "=f"(lo), "=f"(hi) : "l"(v));
}
__device__ __forceinline__ float ldcg_f(const float* p) {
    float v;
    asm volatile("ld.global.cg.f32 %0, [%1];" : "=f"(v) : "l"(p));
    return v;
}

// monotonic global barrier: replay-safe, no reset needed
__device__ __forceinline__ void gbarrier(int k) {
    __syncthreads();
    if (threadIdx.x == 0) {
        __threadfence();
        int old = atomicAdd(&d_bar[k], 1);
        int target = (old / GRID + 1) * GRID;
        int v;
        do {
            asm volatile("ld.acquire.gpu.global.s32 %0, [%1];"
                         : "=r"(v) : "l"(&d_bar[k]));
        } while (v < target);
    }
    __syncthreads();
}

// ---------------- the one kernel --------------------------------------------
__global__ void __launch_bounds__(NT) mega(
        const float* __restrict__ x,  const float* __restrict__ w0,
        const float* __restrict__ g0, const float* __restrict__ b0,
        const float* __restrict__ w1, const float* __restrict__ g1,
        const float* __restrict__ b1, const float* __restrict__ w2,
        const float* __restrict__ g2, const float* __restrict__ b2,
        const float* __restrict__ fw, const float* __restrict__ fb,
        float* __restrict__ out) {
    __shared__ float xs[30][32];       // zero-padded input image
    __shared__ float ws[288];          // conv0 weights
    __shared__ float ss[14][33], sq[14][33];
    __shared__ __align__(16) unsigned X1p[16][16];   // padded sign bitmap (14x14)
    __shared__ __align__(16) unsigned X2p[9][9];     // padded sign bitmap (7x7)
    __shared__ unsigned Wb1[288], Wb2[288];
    __shared__ float h1s[49][32];
    __shared__ float bnS[3][32], bnB[3][32];

    const int t = threadIdx.x, lane = t & 31, w = t >> 5, blk = blockIdx.x;

    // ---- init: zero padded buffers (borders stay 0 forever), load/pack weights
    for (int i = t; i < 960; i += NT) ((float*)xs)[i] = 0.f;
    for (int i = t; i < 256; i += NT) ((unsigned*)X1p)[i] = 0u;
    if (t < 81) ((unsigned*)X2p)[t] = 0u;
    if (t < 288) ws[t] = w0[t];
    for (int task = w; task < 576; task += 14) {     // lane = input channel
        const float* wsrc = (task < 288) ? w1 : w2;
        int r = (task < 288) ? task : task - 288;
        int o = r / 9, tap = r % 9;
        unsigned bal = __ballot_sync(FULL, wsrc[o*288 + lane*9 + tap] > 0.f);
        if (lane == 0) ((task < 288) ? Wb1 : Wb2)[r] = bal;
    }
    __syncthreads();

    // =================== P1: conv0 (Cin=1, pad=1) + 2x2 pool + stats ========
    {
        unsigned long long wp[9];
#pragma unroll
        for (int k = 0; k < 9; k++) { float wv = ws[lane*9 + k]; wp[k] = pk2(wv, wv); }
        float s1 = 0.f, q1 = 0.f;
        const int py = w;              // warp = pooled row
        for (int img = blk; img < B; img += GRID) {
            __syncthreads();           // previous image's compute done
            const float* xb = x + img*784;
            for (int i = t; i < 784; i += NT) {
                int r = i / 28;
                xs[r + 1][i - r*28 + 1] = xb[i];
            }
            __syncthreads();
            float* outp = d_t0 + (((long)img*14 + py)*14)*32 + lane;
#pragma unroll
            for (int j2 = 0; j2 < 7; j2++) {
                unsigned long long a00 = 0ull, a01 = 0ull, a10 = 0ull, a11 = 0ull;
#pragma unroll
                for (int r = 0; r < 4; r++) {
                    float e0 = xs[2*py + r][4*j2 + 0];
                    float e1 = xs[2*py + r][4*j2 + 1];
                    float e2 = xs[2*py + r][4*j2 + 2];
                    float e3 = xs[2*py + r][4*j2 + 3];
                    float e4 = xs[2*py + r][4*j2 + 4];
                    float e5 = xs[2*py + r][4*j2 + 5];
                    unsigned long long Q0 = pk2(e0, e1), Q1 = pk2(e1, e2),
                                       Q2 = pk2(e2, e3), Q3 = pk2(e3, e4),
                                       Q4 = pk2(e4, e5);
                    if (r < 3) {
                        a00 = fma2(wp[r*3+0], Q0, a00);
                        a00 = fma2(wp[r*3+1], Q1, a00);
                        a00 = fma2(wp[r*3+2], Q2, a00);
                        a01 = fma2(wp[r*3+0], Q2, a01);
                        a01 = fma2(wp[r*3+1], Q3, a01);
                        a01 = fma2(wp[r*3+2], Q4, a01);
                    }
                    if (r >= 1) {
                        int k = (r-1)*3;
                        a10 = fma2(wp[k+0], Q0, a10);
                        a10 = fma2(wp[k+1], Q1, a10);
                        a10 = fma2(wp[k+2], Q2, a10);
                        a11 = fma2(wp[k+0], Q2, a11);
                        a11 = fma2(wp[k+1], Q3, a11);
                        a11 = fma2(wp[k+2], Q4, a11);
                    }
                }
                float l0, h0, l1, h1;
                upk2(a00, l0, h0); upk2(a10, l1, h1);
                float m0 = fmaxf(fmaxf(l0, h0), fmaxf(l1, h1));
                upk2(a01, l0, h0); upk2(a11, l1, h1);
                float m1 = fmaxf(fmaxf(l0, h0), fmaxf(l1, h1));
                outp[(2*j2 + 0)*32] = m0;
                outp[(2*j2 + 1)*32] = m1;
                s1 += m0 + m1;
                q1 = fmaf(m0, m0, q1); q1 = fmaf(m1, m1, q1);
            }
        }
        __syncthreads();
        ss[w][lane] = s1; sq[w][lane] = q1;
        __syncthreads();
        if (t < 32) {
            float ts = 0.f, tq = 0.f;
#pragma unroll
            for (int j = 0; j < 14; j++) { ts += ss[j][t]; tq += sq[j][t]; }
            d_psA[0][t*GRID + blk] = ts;
            d_pqA[0][t*GRID + blk] = tq;
        }
    }
    gbarrier(0);
    // finalize BN0 (every block, redundantly; ldcg to bypass L1)
    if (t < 32) {
        double s = 0.0, q = 0.0;
        for (int i = 0; i < GRID; i += 4) {
            s += (double)ldcg_f(&d_psA[0][t*GRID+i])   + (double)ldcg_f(&d_psA[0][t*GRID+i+1])
               + (double)ldcg_f(&d_psA[0][t*GRID+i+2]) + (double)ldcg_f(&d_psA[0][t*GRID+i+3]);
            q += (double)ldcg_f(&d_pqA[0][t*GRID+i])   + (double)ldcg_f(&d_pqA[0][t*GRID+i+1])
               + (double)ldcg_f(&d_pqA[0][t*GRID+i+2]) + (double)ldcg_f(&d_pqA[0][t*GRID+i+3]);
        }
        double n = (double)B * 196.0;
        double mean = s / n, var = q / n - mean * mean;
        double sc = (double)g0[t] / sqrt(var + 1e-5);
        bnS[0][t] = (float)sc;
        bnB[0][t] = (float)((double)b0[t] - mean * sc);
    }
    __syncthreads();

    // =================== P2: pack X1 + p1 + binary conv1 + pool + stats =====
    {
        unsigned wb[9]; int Kc[9];
#pragma unroll
        for (int k = 0; k < 9; k++) { wb[k] = Wb1[lane*9 + k]; Kc[k] = 32 - 2*__popc(wb[k]); }
        int Kt = Kc[0]+Kc[1]+Kc[2], Kb = Kc[6]+Kc[7]+Kc[8];
        int Kl = Kc[0]+Kc[3]+Kc[6], Kr = Kc[2]+Kc[5]+Kc[8];
        float sc = bnS[0][lane], bs = bnB[0][lane];
        float s2 = 0.f, q2 = 0.f;
        for (int img = blk; img < B; img += GRID) {
            // pack sign bits + shortcut pool
            for (int j = w; j < 49; j += 14) {
                int pyy = j / 7, pxx = j % 7;
                float hmax = -INFINITY;
                unsigned myw = 0;
#pragma unroll
                for (int d = 0; d < 4; d++) {
                    int y = 2*pyy + (d >> 1), xx = 2*pxx + (d & 1);
                    float v = d_t0[(((long)img*14 + y)*14 + xx)*32 + lane];
                    float h = fmaf(sc, v, bs);
                    unsigned bal = __ballot_sync(FULL, h > 0.f);
                    if (lane == d) myw = bal;
                    hmax = fmaxf(hmax, h);
                }
                if (lane < 4) X1p[2*pyy + (lane>>1) + 1][2*pxx + (lane&1) + 1] = myw;
                d_p1[(img*49 + j)*32 + lane] = hmax;
            }
            __syncthreads();
            // binary conv + pool from smem bitmap
            for (int j = w; j < 49; j += 14) {
                int pyy = j / 7, pxx = j % 7;
                unsigned xw[4][4];
#pragma unroll
                for (int r4 = 0; r4 < 4; r4++) {
                    const uint2* Xr = reinterpret_cast<const uint2*>(&X1p[2*pyy + r4][2*pxx]);
                    uint2 lo = Xr[0], hi = Xr[1];
                    xw[r4][0] = lo.x; xw[r4][1] = lo.y; xw[r4][2] = hi.x; xw[r4][3] = hi.y;
                }
                int vv[4];
#pragma unroll
                for (int dy = 0; dy < 2; dy++)
#pragma unroll
                    for (int dx = 0; dx < 2; dx++) {
                        int sump = 0;
#pragma unroll
                        for (int ky = 0; ky < 3; ky++)
#pragma unroll
                            for (int kx = 0; kx < 3; kx++)
                                sump += __popc(xw[dy+ky][dx+kx] ^ wb[ky*3+kx]);
                        vv[dy*2+dx] = 288 - 2*sump;
                    }
                if (pyy == 0 || pyy == 6 || pxx == 0 || pxx == 6) {  // warp-uniform
#pragma unroll
                    for (int dy = 0; dy < 2; dy++)
#pragma unroll
                        for (int dx = 0; dx < 2; dx++) {
                            bool top = (pyy == 0) && (dy == 0);
                            bool bot = (pyy == 6) && (dy == 1);
                            bool lef = (pxx == 0) && (dx == 0);
                            bool rig = (pxx == 6) && (dx == 1);
                            int corr = 0;
                            if (top) corr += Kt;
                            if (bot) corr += Kb;
                            if (lef) corr += Kl;
                            if (rig) corr += Kr;
                            if (top && lef) corr -= Kc[0];
                            if (top && rig) corr -= Kc[2];
                            if (bot && lef) corr -= Kc[6];
                            if (bot && rig) corr -= Kc[8];
                            vv[dy*2+dx] -= corr;
                        }
                }
                int m = max(max(vv[0], vv[1]), max(vv[2], vv[3]));
                float fm = (float)m;
                d_u1[(img*49 + j)*32 + lane] = fm;
                s2 += fm; q2 = fmaf(fm, fm, q2);
            }
            __syncthreads();           // X1p reusable for next image
        }
        __syncthreads();
        ss[w][lane] = s2; sq[w][lane] = q2;
        __syncthreads();
        if (t < 32) {
            float ts = 0.f, tq = 0.f;
#pragma unroll
            for (int j = 0; j < 14; j++) { ts += ss[j][t]; tq += sq[j][t]; }
            d_psA[1][t*GRID + blk] = ts;
            d_pqA[1][t*GRID + blk] = tq;
        }
    }
    gbarrier(1);
    if (t < 32) {
        double s = 0.0, q = 0.0;
        for (int i = 0; i < GRID; i += 4) {
            s += (double)ldcg_f(&d_psA[1][t*GRID+i])   + (double)ldcg_f(&d_psA[1][t*GRID+i+1])
               + (double)ldcg_f(&d_psA[1][t*GRID+i+2]) + (double)ldcg_f(&d_psA[1][t*GRID+i+3]);
            q += (double)ldcg_f(&d_pqA[1][t*GRID+i])   + (double)ldcg_f(&d_pqA[1][t*GRID+i+1])
               + (double)ldcg_f(&d_pqA[1][t*GRID+i+2]) + (double)ldcg_f(&d_pqA[1][t*GRID+i+3]);
        }
        double n = (double)B * 49.0;
        double mean = s / n, var = q / n - mean * mean;
        double sc = (double)g1[t] / sqrt(var + 1e-5);
        bnS[1][t] = (float)sc;
        bnB[1][t] = (float)((double)b1[t] - mean * sc);
    }
    __syncthreads();

    // =================== P3: h1 + X2 + p2 + binary conv2 + stats ============
    {
        unsigned wb[9];
#pragma unroll
        for (int k = 0; k < 9; k++) wb[k] = Wb2[lane*9 + k];
        int Kc0 = 32 - 2*__popc(wb[0]);
        int Kc1 = 32 - 2*__popc(wb[1]);
        int Kc2 = 32 - 2*__popc(wb[2]);
        int Kc3 = 32 - 2*__popc(wb[3]);
        int Kc6 = 32 - 2*__popc(wb[6]);
        int Kt = Kc0 + Kc1 + Kc2, Kl = Kc0 + Kc3 + Kc6;
        float sc = bnS[1][lane], bs = bnB[1][lane];
        float s3 = 0.f, q3 = 0.f;
        for (int img = blk; img < B; img += GRID) {
            for (int j = w; j < 49; j += 14) {
                float hv = fmaf(sc, d_u1[(img*49 + j)*32 + lane], bs)
                         + d_p1[(img*49 + j)*32 + lane];
                h1s[j][lane] = hv;
                unsigned bal = __ballot_sync(FULL, hv > 0.f);
                if (lane == 0) X2p[j/7 + 1][j%7 + 1] = bal;
            }
            __syncthreads();
            if (w < 9) {
                int pyy = w / 3, pxx = w % 3;
                int i0 = (2*pyy)*7 + 2*pxx;
                float m = fmaxf(fmaxf(h1s[i0][lane],   h1s[i0+1][lane]),
                                fmaxf(h1s[i0+7][lane], h1s[i0+8][lane]));
                d_p2[(img*9 + w)*32 + lane] = m;
                unsigned xw[4][4];
#pragma unroll
                for (int r4 = 0; r4 < 4; r4++)
#pragma unroll
                    for (int c4 = 0; c4 < 4; c4++)
                        xw[r4][c4] = X2p[2*pyy + r4][2*pxx + c4];
                int mm = -100000;
#pragma unroll
                for (int dy = 0; dy < 2; dy++)
#pragma unroll
                    for (int dx = 0; dx < 2; dx++) {
                        int sump = 0;
#pragma unroll
                        for (int ky = 0; ky < 3; ky++)
#pragma unroll
                            for (int kx = 0; kx < 3; kx++)
                                sump += __popc(xw[dy+ky][dx+kx] ^ wb[ky*3+kx]);
                        int v = 288 - 2*sump;
                        bool top = (pyy == 0) && (dy == 0);
                        bool lef = (pxx == 0) && (dx == 0);
                        int corr = 0;
                        if (top) corr += Kt;
                        if (lef) corr += Kl;
                        if (top && lef) corr -= Kc0;
                        mm = max(mm, v - corr);
                    }
                float fm = (float)mm;
                d_u2[(img*9 + w)*32 + lane] = fm;
                s3 += fm; q3 = fmaf(fm, fm, q3);
            }
            __syncthreads();
        }
        __syncthreads();
        ss[w][lane] = s3; sq[w][lane] = q3;
        __syncthreads();
        if (t < 32) {
            float ts = 0.f, tq = 0.f;
#pragma unroll
            for (int j = 0; j < 14; j++) { ts += ss[j][t]; tq += sq[j][t]; }
            d_psA[2][t*GRID + blk] = ts;
            d_pqA[2][t*GRID + blk] = tq;
        }
    }
    gbarrier(2);
    if (t < 32) {
        double s = 0.0, q = 0.0;
        for (int i = 0; i < GRID; i += 4) {
            s += (double)ldcg_f(&d_psA[2][t*GRID+i])   + (double)ldcg_f(&d_psA[2][t*GRID+i+1])
               + (double)ldcg_f(&d_psA[2][t*GRID+i+2]) + (double)ldcg_f(&d_psA[2][t*GRID+i+3]);
        q += (double)ldcg_f(&d_pqA[2][t*GRID+i])   + (double)ldcg_f(&d_pqA[2][t*GRID+i+1])
               + (double)ldcg_f(&d_pqA[2][t*GRID+i+2]) + (double)ldcg_f(&d_pqA[2][t*GRID+i+3]);
        }
        double n = (double)B * 9.0;
        double mean = s / n, var = q / n - mean * mean;
        double sc = (double)g2[t] / sqrt(var + 1e-5);
        bnS[2][t] = (float)sc;
        bnB[2][t] = (float)((double)b2[t] - mean * sc);
    }
    __syncthreads();

    // =================== P4: fused h2 = bn(u2)+p2, flatten, FC ==============
    {
        float sc = bnS[2][lane], bs = bnB[2][lane];
        for (int b = blk*14 + w; b < B; b += GRID*14) {
            float acc[10];
#pragma unroll
            for (int k = 0; k < 10; k++) acc[k] = 0.f;
#pragma unroll
            for (int ij = 0; ij < 9; ij++) {
                float h = fmaf(sc, ldcg_f(&d_u2[(b*9 + ij)*32 + lane]), bs)
                        + ldcg_f(&d_p2[(b*9 + ij)*32 + lane]);
#pragma unroll
                for (int k = 0; k < 10; k++)
                    acc[k] = fmaf(h, fw[k*288 + lane*9 + ij], acc[k]);
            }
#pragma unroll
            for (int k = 0; k < 10; k++) {
#pragma unroll
                for (int off = 16; off; off >>= 1)
                    acc[k] += __shfl_xor_sync(FULL, acc[k], off);
                if (lane == k) out[b*10 + k] = acc[k] + fb[k];
            }
        }
    }
}

// ---------------- launch -----------------------------------------------------
extern "C" void kernel_launch(void* const* d_in, const int* in_sizes, int n_in,
                              void* d_out, int out_size) {
    const float* x  = (const float*)d_in[0];
    const float* w0 = (const float*)d_in[1];
    const float* g0 = (const float*)d_in[2];
    const float* b0 = (const float*)d_in[3];
    const float* w1 = (const float*)d_in[4];
    const float* g1 = (const float*)d_in[5];
    const float* b1 = (const float*)d_in[6];
    const float* w2 = (const float*)d_in[7];
    const float* g2 = (const float*)d_in[8];
    const float* b2 = (const float*)d_in[9];
    const float* fw = (const float*)d_in[10];
    const float* fb = (const float*)d_in[11];
    float* out = (float*)d_out;

    mega<<<GRID, NT>>>(x, w0, g0, b0, w1, g1, b1, w2, g2, b2, fw, fb, out);
}